// round 9
// baseline (speedup 1.0000x reference)
#include <cuda_runtime.h>
#include <math.h>

// Problem constants (fixed by the reference)
#define NN 100000     // nodes
#define EE 1600000    // edges
#define FI 32         // input features
#define HH 16         // hidden
#define CC 10         // classes
#define CP 12         // padded classes

// ---------------- device scratch (static; no allocation allowed) -------------
__device__ int  g_is64;
__device__ int  g_cnt[NN];
__device__ int  g_off[NN + 1];
__device__ int  g_cur[NN];
__device__ int2 g_ev[EE];                         // (src, float_as_int(v)) sorted by dst

__device__ __align__(16) float g_YY[NN * 32];     // interleaved [Y0[16] | Yd[16]]
__device__ __align__(16) float g_R1[NN * HH];     // x @ root1 + b1
__device__ __align__(16) float g_H [NN * HH];     // hidden after ELU

__device__ __align__(16) float g_ZZ[NN * 24];     // interleaved [Z0[12] | Zd[12]]
__device__ __align__(16) float g_R2[NN * CP];     // h @ root2 + b2 (padded)

// ---------------- dtype detect: int64 vs int32 edge_index --------------------
__global__ void k_detect(const int* __restrict__ ei32) {
    __shared__ int s_any;
    if (threadIdx.x == 0) s_any = 0;
    __syncthreads();
    int v = 0;
    for (int i = 2 * threadIdx.x + 1; i < 4096; i += 2 * blockDim.x) v |= ei32[i];
    if (v) atomicOr(&s_any, 1);
    __syncthreads();
    if (threadIdx.x == 0) g_is64 = (s_any == 0) ? 1 : 0;
}

// ---------------- CSR build ---------------------------------------------------
__global__ void k_zero() {
    int i = blockIdx.x * blockDim.x + threadIdx.x;
    if (i < NN) g_cnt[i] = 0;
}

__global__ void k_hist(const void* __restrict__ ei) {
    int e = blockIdx.x * blockDim.x + threadIdx.x;
    if (e >= EE) return;
    int d = g_is64 ? (int)((const long long*)ei)[EE + e] : ((const int*)ei)[EE + e];
    atomicAdd(&g_cnt[d], 1);
}

__global__ void k_scan() {
    __shared__ int sp[1024];
    const int CHUNK = (NN + 1023) / 1024;   // 98
    int tid = threadIdx.x;
    int base = tid * CHUNK;
    int sum = 0;
    for (int i = 0; i < CHUNK; i++) {
        int j = base + i;
        if (j < NN) sum += g_cnt[j];
    }
    sp[tid] = sum;
    __syncthreads();
    for (int d = 1; d < 1024; d <<= 1) {
        int t = (tid >= d) ? sp[tid - d] : 0;
        __syncthreads();
        sp[tid] += t;
        __syncthreads();
    }
    int run = sp[tid] - sum;    // exclusive prefix
    for (int i = 0; i < CHUNK; i++) {
        int j = base + i;
        if (j < NN) {
            g_off[j] = run;
            g_cur[j] = run;
            run += g_cnt[j];
        }
    }
    if (tid == 1023) g_off[NN] = sp[1023];
}

__global__ void k_scatter(const void* __restrict__ ei, const float* __restrict__ attr) {
    int e = blockIdx.x * blockDim.x + threadIdx.x;
    if (e >= EE) return;
    int s, d;
    if (g_is64) {
        const long long* p = (const long long*)ei;
        s = (int)p[e];
        d = (int)p[EE + e];
    } else {
        const int* p = (const int*)ei;
        s = p[e];
        d = p[EE + e];
    }
    float v = attr[e];          // K=2 -> v = attr * (K-1) = attr
    int pos = atomicAdd(&g_cur[d], 1);
    g_ev[pos] = make_int2(s, __float_as_int(v));
}

// ---------------- layer-1 node precompute -------------------------------------
__global__ void k_node1(const float* __restrict__ x, const float* __restrict__ W1,
                        const float* __restrict__ root1, const float* __restrict__ b1) {
    __shared__ float sW0[FI * HH], sWd[FI * HH], sR[FI * HH], sB[HH];
    for (int i = threadIdx.x; i < FI * HH; i += blockDim.x) {
        float w0 = W1[i];
        sW0[i] = w0;
        sWd[i] = W1[FI * HH + i] - w0;
        sR[i]  = root1[i];
    }
    if (threadIdx.x < HH) sB[threadIdx.x] = b1[threadIdx.x];
    __syncthreads();

    int n = blockIdx.x * blockDim.x + threadIdx.x;
    if (n >= NN) return;

    float xr[FI];
    const float4* xp = (const float4*)(x + (size_t)n * FI);
#pragma unroll
    for (int i = 0; i < FI / 4; i++) {
        float4 t = xp[i];
        xr[4 * i + 0] = t.x; xr[4 * i + 1] = t.y;
        xr[4 * i + 2] = t.z; xr[4 * i + 3] = t.w;
    }

    float4 y0[4], yd[4], r1[4];
#pragma unroll
    for (int j = 0; j < 4; j++) {
        y0[j] = make_float4(0.f, 0.f, 0.f, 0.f);
        yd[j] = make_float4(0.f, 0.f, 0.f, 0.f);
        r1[j] = ((const float4*)sB)[j];
    }
#pragma unroll
    for (int i = 0; i < FI; i++) {
        float xi = xr[i];
        const float4* w0 = (const float4*)(sW0 + i * HH);
        const float4* wd = (const float4*)(sWd + i * HH);
        const float4* wr = (const float4*)(sR + i * HH);
#pragma unroll
        for (int j = 0; j < 4; j++) {
            float4 a = w0[j], b = wd[j], c = wr[j];
            y0[j].x = fmaf(xi, a.x, y0[j].x); y0[j].y = fmaf(xi, a.y, y0[j].y);
            y0[j].z = fmaf(xi, a.z, y0[j].z); y0[j].w = fmaf(xi, a.w, y0[j].w);
            yd[j].x = fmaf(xi, b.x, yd[j].x); yd[j].y = fmaf(xi, b.y, yd[j].y);
            yd[j].z = fmaf(xi, b.z, yd[j].z); yd[j].w = fmaf(xi, b.w, yd[j].w);
            r1[j].x = fmaf(xi, c.x, r1[j].x); r1[j].y = fmaf(xi, c.y, r1[j].y);
            r1[j].z = fmaf(xi, c.z, r1[j].z); r1[j].w = fmaf(xi, c.w, r1[j].w);
        }
    }
    float4* oy = (float4*)(g_YY + (size_t)n * 32);
    float4* orr = (float4*)(g_R1 + (size_t)n * HH);
#pragma unroll
    for (int j = 0; j < 4; j++) { oy[j] = y0[j]; oy[4 + j] = yd[j]; orr[j] = r1[j]; }
}

// ---------------- layer-1 gather: warp per node, no atomics --------------------
// lane<16 accumulates Y0[src][lane]; lane>=16 accumulates v*Yd[src][lane-16].
// One 128B fully-coalesced load per edge per warp.
__global__ void k_gath1() {
    int w = (blockIdx.x * blockDim.x + threadIdx.x) >> 5;
    int lane = threadIdx.x & 31;
    if (w >= NN) return;
    int beg = g_off[w], end = g_off[w + 1];

    float acc = 0.f;
    int i = beg;
    for (; i + 3 < end; i += 4) {
        int2 e0 = g_ev[i], e1 = g_ev[i + 1], e2 = g_ev[i + 2], e3 = g_ev[i + 3];
        float v0 = g_YY[(size_t)e0.x * 32 + lane];
        float v1 = g_YY[(size_t)e1.x * 32 + lane];
        float v2 = g_YY[(size_t)e2.x * 32 + lane];
        float v3 = g_YY[(size_t)e3.x * 32 + lane];
        float c0 = (lane < 16) ? 1.f : __int_as_float(e0.y);
        float c1 = (lane < 16) ? 1.f : __int_as_float(e1.y);
        float c2 = (lane < 16) ? 1.f : __int_as_float(e2.y);
        float c3 = (lane < 16) ? 1.f : __int_as_float(e3.y);
        acc = fmaf(c0, v0, acc); acc = fmaf(c1, v1, acc);
        acc = fmaf(c2, v2, acc); acc = fmaf(c3, v3, acc);
    }
    for (; i < end; i++) {
        int2 e0 = g_ev[i];
        float v0 = g_YY[(size_t)e0.x * 32 + lane];
        float c0 = (lane < 16) ? 1.f : __int_as_float(e0.y);
        acc = fmaf(c0, v0, acc);
    }
    acc += __shfl_xor_sync(0xffffffffu, acc, 16);
    if (lane < 16) {
        float rdeg = 1.f / fmaxf((float)(end - beg), 1.f);
        float t = fmaf(acc, rdeg, g_R1[(size_t)w * HH + lane]);
        g_H[(size_t)w * HH + lane] = (t > 0.f) ? t : expm1f(t);
    }
}

// ---------------- layer-2 node precompute --------------------------------------
__global__ void k_node2(const float* __restrict__ W2, const float* __restrict__ root2,
                        const float* __restrict__ b2) {
    __shared__ float sZ0[HH * CP], sZd[HH * CP], sR[HH * CP], sB[CP];
    for (int idx = threadIdx.x; idx < HH * CP; idx += blockDim.x) {
        int i = idx / CP, c = idx % CP;
        float w0 = (c < CC) ? W2[i * CC + c] : 0.f;
        float w1 = (c < CC) ? W2[HH * CC + i * CC + c] : 0.f;
        sZ0[idx] = w0;
        sZd[idx] = w1 - w0;
        sR[idx]  = (c < CC) ? root2[i * CC + c] : 0.f;
    }
    if (threadIdx.x < CP) sB[threadIdx.x] = (threadIdx.x < CC) ? b2[threadIdx.x] : 0.f;
    __syncthreads();

    int n = blockIdx.x * blockDim.x + threadIdx.x;
    if (n >= NN) return;

    float h[HH];
    const float4* hp = (const float4*)(g_H + (size_t)n * HH);
#pragma unroll
    for (int j = 0; j < 4; j++) {
        float4 t = hp[j];
        h[4 * j + 0] = t.x; h[4 * j + 1] = t.y;
        h[4 * j + 2] = t.z; h[4 * j + 3] = t.w;
    }

    float4 z0[3], zd[3], r2[3];
#pragma unroll
    for (int j = 0; j < 3; j++) {
        z0[j] = make_float4(0.f, 0.f, 0.f, 0.f);
        zd[j] = make_float4(0.f, 0.f, 0.f, 0.f);
        r2[j] = ((const float4*)sB)[j];
    }
#pragma unroll
    for (int i = 0; i < HH; i++) {
        float hi = h[i];
        const float4* a = (const float4*)(sZ0 + i * CP);
        const float4* b = (const float4*)(sZd + i * CP);
        const float4* c = (const float4*)(sR + i * CP);
#pragma unroll
        for (int j = 0; j < 3; j++) {
            float4 wa = a[j], wb = b[j], wc = c[j];
            z0[j].x = fmaf(hi, wa.x, z0[j].x); z0[j].y = fmaf(hi, wa.y, z0[j].y);
            z0[j].z = fmaf(hi, wa.z, z0[j].z); z0[j].w = fmaf(hi, wa.w, z0[j].w);
            zd[j].x = fmaf(hi, wb.x, zd[j].x); zd[j].y = fmaf(hi, wb.y, zd[j].y);
            zd[j].z = fmaf(hi, wb.z, zd[j].z); zd[j].w = fmaf(hi, wb.w, zd[j].w);
            r2[j].x = fmaf(hi, wc.x, r2[j].x); r2[j].y = fmaf(hi, wc.y, r2[j].y);
            r2[j].z = fmaf(hi, wc.z, r2[j].z); r2[j].w = fmaf(hi, wc.w, r2[j].w);
        }
    }
    float4* oz = (float4*)(g_ZZ + (size_t)n * 24);
    float4* orr = (float4*)(g_R2 + (size_t)n * CP);
#pragma unroll
    for (int j = 0; j < 3; j++) { oz[j] = z0[j]; oz[3 + j] = zd[j]; orr[j] = r2[j]; }
}

// ---------------- layer-2 gather + log_softmax: warp per node, no atomics ------
// Records are 24 floats (96B, 32B-sector aligned): lanes 0-11 Z0, lanes 12-23 v*Zd.
__global__ void k_gath2(float* __restrict__ out) {
    int w = (blockIdx.x * blockDim.x + threadIdx.x) >> 5;
    int lane = threadIdx.x & 31;
    if (w >= NN) return;
    int beg = g_off[w], end = g_off[w + 1];
    bool act = (lane < 24);

    float acc = 0.f;
    int i = beg;
    for (; i + 3 < end; i += 4) {
        int2 e0 = g_ev[i], e1 = g_ev[i + 1], e2 = g_ev[i + 2], e3 = g_ev[i + 3];
        float v0 = act ? g_ZZ[(size_t)e0.x * 24 + lane] : 0.f;
        float v1 = act ? g_ZZ[(size_t)e1.x * 24 + lane] : 0.f;
        float v2 = act ? g_ZZ[(size_t)e2.x * 24 + lane] : 0.f;
        float v3 = act ? g_ZZ[(size_t)e3.x * 24 + lane] : 0.f;
        float c0 = (lane < 12) ? 1.f : __int_as_float(e0.y);
        float c1 = (lane < 12) ? 1.f : __int_as_float(e1.y);
        float c2 = (lane < 12) ? 1.f : __int_as_float(e2.y);
        float c3 = (lane < 12) ? 1.f : __int_as_float(e3.y);
        acc = fmaf(c0, v0, acc); acc = fmaf(c1, v1, acc);
        acc = fmaf(c2, v2, acc); acc = fmaf(c3, v3, acc);
    }
    for (; i < end; i++) {
        int2 e0 = g_ev[i];
        float v0 = act ? g_ZZ[(size_t)e0.x * 24 + lane] : 0.f;
        float c0 = (lane < 12) ? 1.f : __int_as_float(e0.y);
        acc = fmaf(c0, v0, acc);
    }
    // combine Z0-part (lanes 0-11) with v*Zd-part (lanes 12-23)
    float other = __shfl_down_sync(0xffffffffu, acc, 12);
    float rdeg = 1.f / fmaxf((float)(end - beg), 1.f);
    float u = 0.f;
    if (lane < CP)
        u = fmaf(acc + other, rdeg, g_R2[(size_t)w * CP + lane]);

    // log_softmax across lanes 0-9 (width-16 butterflies; pads neutral)
    float um = (lane < CC) ? u : -1e30f;
#pragma unroll
    for (int d = 1; d < 16; d <<= 1)
        um = fmaxf(um, __shfl_xor_sync(0xffffffffu, um, d, 16));
    float ex = (lane < CC) ? __expf(u - um) : 0.f;
    float s = ex;
#pragma unroll
    for (int d = 1; d < 16; d <<= 1)
        s += __shfl_xor_sync(0xffffffffu, s, d, 16);
    float lse = um + logf(s);
    if (lane < CC) out[(size_t)w * CC + lane] = u - lse;
}

// ---------------- launch ------------------------------------------------------
extern "C" void kernel_launch(void* const* d_in, const int* in_sizes, int n_in,
                              void* d_out, int out_size) {
    const float* x     = (const float*)d_in[0];
    const void*  ei    = d_in[1];
    const float* attr  = (const float*)d_in[2];
    const float* W1    = (const float*)d_in[3];
    const float* root1 = (const float*)d_in[4];
    const float* b1    = (const float*)d_in[5];
    const float* W2    = (const float*)d_in[6];
    const float* root2 = (const float*)d_in[7];
    const float* b2    = (const float*)d_in[8];
    float* out = (float*)d_out;

    k_detect<<<1, 256>>>((const int*)ei);
    k_zero<<<(NN + 255) / 256, 256>>>();
    k_hist<<<(EE + 255) / 256, 256>>>(ei);
    k_scan<<<1, 1024>>>();
    k_scatter<<<(EE + 255) / 256, 256>>>(ei, attr);
    k_node1<<<(NN + 127) / 128, 128>>>(x, W1, root1, b1);
    k_gath1<<<(NN * 32 + 255) / 256, 256>>>();
    k_node2<<<(NN + 127) / 128, 128>>>(W2, root2, b2);
    k_gath2<<<(NN * 32 + 255) / 256, 256>>>(out);
}

// round 10
// speedup vs baseline: 1.4109x; 1.4109x over previous
#include <cuda_runtime.h>
#include <math.h>

// Problem constants (fixed by the reference)
#define NN 100000     // nodes
#define EE 1600000    // edges
#define FI 32         // input features
#define HH 16         // hidden
#define CC 10         // classes
#define CP 12         // padded classes
#define NBLK ((NN + 1023) / 1024)   // 98 scan blocks

// ---------------- device scratch (static; no allocation allowed) -------------
__device__ int  g_is64;
__device__ int  g_cnt[NN];
__device__ int  g_off[NN + 1];
__device__ int  g_cur[NN];
__device__ int  g_bsum[NBLK];
__device__ int  g_total;
__device__ int2 g_ev[EE];                         // (src, float_as_int(v)) sorted by dst

__device__ __align__(16) float g_YY[NN * 32];     // interleaved [Y0[16] | Yd[16]]
__device__ __align__(16) float g_R1[NN * HH];     // x @ root1 + b1
__device__ __align__(16) float g_H [NN * HH];     // hidden after ELU

__device__ __align__(16) float g_ZZ[NN * 24];     // interleaved [Z0[12] | Zd[12]]
__device__ __align__(16) float g_R2[NN * CP];     // h @ root2 + b2 (padded)

// ---------------- detect dtype (block 0) + zero histogram (all blocks) --------
__global__ void k_detect_zero(const int* __restrict__ ei32) {
    int i = blockIdx.x * blockDim.x + threadIdx.x;
    if (i < NN) g_cnt[i] = 0;
    if (blockIdx.x == 0) {
        __shared__ int s_any;
        if (threadIdx.x == 0) s_any = 0;
        __syncthreads();
        int v = 0;
        for (int j = 2 * threadIdx.x + 1; j < 4096; j += 2 * blockDim.x) v |= ei32[j];
        if (v) atomicOr(&s_any, 1);
        __syncthreads();
        if (threadIdx.x == 0) g_is64 = (s_any == 0) ? 1 : 0;
    }
}

// ---------------- CSR build ---------------------------------------------------
__global__ void k_hist(const void* __restrict__ ei) {
    int e = blockIdx.x * blockDim.x + threadIdx.x;
    if (e >= EE) return;
    int d = g_is64 ? (int)((const long long*)ei)[EE + e] : ((const int*)ei)[EE + e];
    atomicAdd(&g_cnt[d], 1);
}

// Phase 1: per-block (1024-wide) exclusive scan of g_cnt -> g_off, block sums.
__global__ void k_scan_blk() {
    __shared__ int wsum[32];
    int i = blockIdx.x * 1024 + threadIdx.x;
    int lane = threadIdx.x & 31, wid = threadIdx.x >> 5;
    int v = (i < NN) ? g_cnt[i] : 0;
    int s = v;
#pragma unroll
    for (int d = 1; d < 32; d <<= 1) {
        int t = __shfl_up_sync(0xffffffffu, s, d);
        if (lane >= d) s += t;
    }
    if (lane == 31) wsum[wid] = s;
    __syncthreads();
    if (wid == 0) {
        int ws = wsum[lane];
#pragma unroll
        for (int d = 1; d < 32; d <<= 1) {
            int t = __shfl_up_sync(0xffffffffu, ws, d);
            if (lane >= d) ws += t;
        }
        wsum[lane] = ws;    // inclusive across warps
    }
    __syncthreads();
    int wpre = (wid == 0) ? 0 : wsum[wid - 1];
    if (i < NN) g_off[i] = wpre + s - v;          // block-local exclusive
    if (threadIdx.x == 1023) g_bsum[blockIdx.x] = wsum[31];
}

// Phase 2: scan the NBLK block sums (single small block).
__global__ void k_scan_top() {
    __shared__ int wsum[4];
    int tid = threadIdx.x;                        // 128 threads
    int lane = tid & 31, wid = tid >> 5;
    int v = (tid < NBLK) ? g_bsum[tid] : 0;
    int s = v;
#pragma unroll
    for (int d = 1; d < 32; d <<= 1) {
        int t = __shfl_up_sync(0xffffffffu, s, d);
        if (lane >= d) s += t;
    }
    if (lane == 31) wsum[wid] = s;
    __syncthreads();
    int wpre = 0;
    for (int j = 0; j < wid; j++) wpre += wsum[j];
    __syncthreads();
    if (tid < NBLK) g_bsum[tid] = wpre + s - v;   // exclusive block prefix
    if (tid == 127) g_total = wpre + s;           // grand total (pads are 0)
}

// Phase 3: add block prefixes, materialize g_off / g_cur.
__global__ void k_scan_add() {
    int i = blockIdx.x * blockDim.x + threadIdx.x;
    if (i < NN) {
        int o = g_off[i] + g_bsum[i >> 10];
        g_off[i] = o;
        g_cur[i] = o;
    }
    if (i == 0) g_off[NN] = g_total;
}

__global__ void k_scatter(const void* __restrict__ ei, const float* __restrict__ attr) {
    int e = blockIdx.x * blockDim.x + threadIdx.x;
    if (e >= EE) return;
    int s, d;
    if (g_is64) {
        const long long* p = (const long long*)ei;
        s = (int)p[e];
        d = (int)p[EE + e];
    } else {
        const int* p = (const int*)ei;
        s = p[e];
        d = p[EE + e];
    }
    float v = attr[e];          // K=2 -> v = attr * (K-1) = attr
    int pos = atomicAdd(&g_cur[d], 1);
    g_ev[pos] = make_int2(s, __float_as_int(v));
}

// ---------------- layer-1 node precompute -------------------------------------
__global__ void k_node1(const float* __restrict__ x, const float* __restrict__ W1,
                        const float* __restrict__ root1, const float* __restrict__ b1) {
    __shared__ float sW0[FI * HH], sWd[FI * HH], sR[FI * HH], sB[HH];
    for (int i = threadIdx.x; i < FI * HH; i += blockDim.x) {
        float w0 = W1[i];
        sW0[i] = w0;
        sWd[i] = W1[FI * HH + i] - w0;
        sR[i]  = root1[i];
    }
    if (threadIdx.x < HH) sB[threadIdx.x] = b1[threadIdx.x];
    __syncthreads();

    int n = blockIdx.x * blockDim.x + threadIdx.x;
    if (n >= NN) return;

    float xr[FI];
    const float4* xp = (const float4*)(x + (size_t)n * FI);
#pragma unroll
    for (int i = 0; i < FI / 4; i++) {
        float4 t = xp[i];
        xr[4 * i + 0] = t.x; xr[4 * i + 1] = t.y;
        xr[4 * i + 2] = t.z; xr[4 * i + 3] = t.w;
    }

    float4 y0[4], yd[4], r1[4];
#pragma unroll
    for (int j = 0; j < 4; j++) {
        y0[j] = make_float4(0.f, 0.f, 0.f, 0.f);
        yd[j] = make_float4(0.f, 0.f, 0.f, 0.f);
        r1[j] = ((const float4*)sB)[j];
    }
#pragma unroll
    for (int i = 0; i < FI; i++) {
        float xi = xr[i];
        const float4* w0 = (const float4*)(sW0 + i * HH);
        const float4* wd = (const float4*)(sWd + i * HH);
        const float4* wr = (const float4*)(sR + i * HH);
#pragma unroll
        for (int j = 0; j < 4; j++) {
            float4 a = w0[j], b = wd[j], c = wr[j];
            y0[j].x = fmaf(xi, a.x, y0[j].x); y0[j].y = fmaf(xi, a.y, y0[j].y);
            y0[j].z = fmaf(xi, a.z, y0[j].z); y0[j].w = fmaf(xi, a.w, y0[j].w);
            yd[j].x = fmaf(xi, b.x, yd[j].x); yd[j].y = fmaf(xi, b.y, yd[j].y);
            yd[j].z = fmaf(xi, b.z, yd[j].z); yd[j].w = fmaf(xi, b.w, yd[j].w);
            r1[j].x = fmaf(xi, c.x, r1[j].x); r1[j].y = fmaf(xi, c.y, r1[j].y);
            r1[j].z = fmaf(xi, c.z, r1[j].z); r1[j].w = fmaf(xi, c.w, r1[j].w);
        }
    }
    float4* oy = (float4*)(g_YY + (size_t)n * 32);
    float4* orr = (float4*)(g_R1 + (size_t)n * HH);
#pragma unroll
    for (int j = 0; j < 4; j++) { oy[j] = y0[j]; oy[4 + j] = yd[j]; orr[j] = r1[j]; }
}

// ---------------- layer-1 gather: warp per node, no atomics --------------------
__global__ void k_gath1() {
    int w = (blockIdx.x * blockDim.x + threadIdx.x) >> 5;
    int lane = threadIdx.x & 31;
    if (w >= NN) return;
    int beg = g_off[w], end = g_off[w + 1];

    float acc = 0.f;
    int i = beg;
    for (; i + 3 < end; i += 4) {
        int2 e0 = g_ev[i], e1 = g_ev[i + 1], e2 = g_ev[i + 2], e3 = g_ev[i + 3];
        float v0 = g_YY[(size_t)e0.x * 32 + lane];
        float v1 = g_YY[(size_t)e1.x * 32 + lane];
        float v2 = g_YY[(size_t)e2.x * 32 + lane];
        float v3 = g_YY[(size_t)e3.x * 32 + lane];
        float c0 = (lane < 16) ? 1.f : __int_as_float(e0.y);
        float c1 = (lane < 16) ? 1.f : __int_as_float(e1.y);
        float c2 = (lane < 16) ? 1.f : __int_as_float(e2.y);
        float c3 = (lane < 16) ? 1.f : __int_as_float(e3.y);
        acc = fmaf(c0, v0, acc); acc = fmaf(c1, v1, acc);
        acc = fmaf(c2, v2, acc); acc = fmaf(c3, v3, acc);
    }
    for (; i < end; i++) {
        int2 e0 = g_ev[i];
        float v0 = g_YY[(size_t)e0.x * 32 + lane];
        float c0 = (lane < 16) ? 1.f : __int_as_float(e0.y);
        acc = fmaf(c0, v0, acc);
    }
    acc += __shfl_xor_sync(0xffffffffu, acc, 16);
    if (lane < 16) {
        float rdeg = 1.f / fmaxf((float)(end - beg), 1.f);
        float t = fmaf(acc, rdeg, g_R1[(size_t)w * HH + lane]);
        g_H[(size_t)w * HH + lane] = (t > 0.f) ? t : expm1f(t);
    }
}

// ---------------- layer-2 node precompute --------------------------------------
__global__ void k_node2(const float* __restrict__ W2, const float* __restrict__ root2,
                        const float* __restrict__ b2) {
    __shared__ float sZ0[HH * CP], sZd[HH * CP], sR[HH * CP], sB[CP];
    for (int idx = threadIdx.x; idx < HH * CP; idx += blockDim.x) {
        int i = idx / CP, c = idx % CP;
        float w0 = (c < CC) ? W2[i * CC + c] : 0.f;
        float w1 = (c < CC) ? W2[HH * CC + i * CC + c] : 0.f;
        sZ0[idx] = w0;
        sZd[idx] = w1 - w0;
        sR[idx]  = (c < CC) ? root2[i * CC + c] : 0.f;
    }
    if (threadIdx.x < CP) sB[threadIdx.x] = (threadIdx.x < CC) ? b2[threadIdx.x] : 0.f;
    __syncthreads();

    int n = blockIdx.x * blockDim.x + threadIdx.x;
    if (n >= NN) return;

    float h[HH];
    const float4* hp = (const float4*)(g_H + (size_t)n * HH);
#pragma unroll
    for (int j = 0; j < 4; j++) {
        float4 t = hp[j];
        h[4 * j + 0] = t.x; h[4 * j + 1] = t.y;
        h[4 * j + 2] = t.z; h[4 * j + 3] = t.w;
    }

    float4 z0[3], zd[3], r2[3];
#pragma unroll
    for (int j = 0; j < 3; j++) {
        z0[j] = make_float4(0.f, 0.f, 0.f, 0.f);
        zd[j] = make_float4(0.f, 0.f, 0.f, 0.f);
        r2[j] = ((const float4*)sB)[j];
    }
#pragma unroll
    for (int i = 0; i < HH; i++) {
        float hi = h[i];
        const float4* a = (const float4*)(sZ0 + i * CP);
        const float4* b = (const float4*)(sZd + i * CP);
        const float4* c = (const float4*)(sR + i * CP);
#pragma unroll
        for (int j = 0; j < 3; j++) {
            float4 wa = a[j], wb = b[j], wc = c[j];
            z0[j].x = fmaf(hi, wa.x, z0[j].x); z0[j].y = fmaf(hi, wa.y, z0[j].y);
            z0[j].z = fmaf(hi, wa.z, z0[j].z); z0[j].w = fmaf(hi, wa.w, z0[j].w);
            zd[j].x = fmaf(hi, wb.x, zd[j].x); zd[j].y = fmaf(hi, wb.y, zd[j].y);
            zd[j].z = fmaf(hi, wb.z, zd[j].z); zd[j].w = fmaf(hi, wb.w, zd[j].w);
            r2[j].x = fmaf(hi, wc.x, r2[j].x); r2[j].y = fmaf(hi, wc.y, r2[j].y);
            r2[j].z = fmaf(hi, wc.z, r2[j].z); r2[j].w = fmaf(hi, wc.w, r2[j].w);
        }
    }
    float4* oz = (float4*)(g_ZZ + (size_t)n * 24);
    float4* orr = (float4*)(g_R2 + (size_t)n * CP);
#pragma unroll
    for (int j = 0; j < 3; j++) { oz[j] = z0[j]; oz[3 + j] = zd[j]; orr[j] = r2[j]; }
}

// ---------------- layer-2 gather + log_softmax: warp per node ------------------
__global__ void k_gath2(float* __restrict__ out) {
    int w = (blockIdx.x * blockDim.x + threadIdx.x) >> 5;
    int lane = threadIdx.x & 31;
    if (w >= NN) return;
    int beg = g_off[w], end = g_off[w + 1];
    bool act = (lane < 24);

    float acc = 0.f;
    int i = beg;
    for (; i + 3 < end; i += 4) {
        int2 e0 = g_ev[i], e1 = g_ev[i + 1], e2 = g_ev[i + 2], e3 = g_ev[i + 3];
        float v0 = act ? g_ZZ[(size_t)e0.x * 24 + lane] : 0.f;
        float v1 = act ? g_ZZ[(size_t)e1.x * 24 + lane] : 0.f;
        float v2 = act ? g_ZZ[(size_t)e2.x * 24 + lane] : 0.f;
        float v3 = act ? g_ZZ[(size_t)e3.x * 24 + lane] : 0.f;
        float c0 = (lane < 12) ? 1.f : __int_as_float(e0.y);
        float c1 = (lane < 12) ? 1.f : __int_as_float(e1.y);
        float c2 = (lane < 12) ? 1.f : __int_as_float(e2.y);
        float c3 = (lane < 12) ? 1.f : __int_as_float(e3.y);
        acc = fmaf(c0, v0, acc); acc = fmaf(c1, v1, acc);
        acc = fmaf(c2, v2, acc); acc = fmaf(c3, v3, acc);
    }
    for (; i < end; i++) {
        int2 e0 = g_ev[i];
        float v0 = act ? g_ZZ[(size_t)e0.x * 24 + lane] : 0.f;
        float c0 = (lane < 12) ? 1.f : __int_as_float(e0.y);
        acc = fmaf(c0, v0, acc);
    }
    float other = __shfl_down_sync(0xffffffffu, acc, 12);
    float rdeg = 1.f / fmaxf((float)(end - beg), 1.f);
    float u = 0.f;
    if (lane < CP)
        u = fmaf(acc + other, rdeg, g_R2[(size_t)w * CP + lane]);

    float um = (lane < CC) ? u : -1e30f;
#pragma unroll
    for (int d = 1; d < 16; d <<= 1)
        um = fmaxf(um, __shfl_xor_sync(0xffffffffu, um, d, 16));
    float ex = (lane < CC) ? __expf(u - um) : 0.f;
    float s = ex;
#pragma unroll
    for (int d = 1; d < 16; d <<= 1)
        s += __shfl_xor_sync(0xffffffffu, s, d, 16);
    float lse = um + logf(s);
    if (lane < CC) out[(size_t)w * CC + lane] = u - lse;
}

// ---------------- launch ------------------------------------------------------
extern "C" void kernel_launch(void* const* d_in, const int* in_sizes, int n_in,
                              void* d_out, int out_size) {
    const float* x     = (const float*)d_in[0];
    const void*  ei    = d_in[1];
    const float* attr  = (const float*)d_in[2];
    const float* W1    = (const float*)d_in[3];
    const float* root1 = (const float*)d_in[4];
    const float* b1    = (const float*)d_in[5];
    const float* W2    = (const float*)d_in[6];
    const float* root2 = (const float*)d_in[7];
    const float* b2    = (const float*)d_in[8];
    float* out = (float*)d_out;

    k_detect_zero<<<(NN + 255) / 256, 256>>>((const int*)ei);
    k_hist<<<(EE + 255) / 256, 256>>>(ei);
    k_scan_blk<<<NBLK, 1024>>>();
    k_scan_top<<<1, 128>>>();
    k_scan_add<<<(NN + 255) / 256, 256>>>();
    k_scatter<<<(EE + 255) / 256, 256>>>(ei, attr);
    k_node1<<<(NN + 127) / 128, 128>>>(x, W1, root1, b1);
    k_gath1<<<(NN * 32 + 255) / 256, 256>>>();
    k_node2<<<(NN + 127) / 128, 128>>>(W2, root2, b2);
    k_gath2<<<(NN * 32 + 255) / 256, 256>>>(out);
}

// round 13
// speedup vs baseline: 1.8641x; 1.3212x over previous
#include <cuda_runtime.h>
#include <math.h>

// Problem constants (fixed by the reference)
#define NN 100000     // nodes
#define EE 1600000    // edges
#define FI 32         // input features
#define HH 16         // hidden
#define CC 10         // classes
#define CP 12         // padded classes
#define NBLK ((NN + 1023) / 1024)       // 98 scan blocks
#define SBLK (EE / 256)                 // 6250 scatter blocks
#define N1BLK ((NN + 255) / 256)        // 391 node blocks

// ---------------- device scratch (static; no allocation allowed) -------------
__device__ int  g_is64;
__device__ int  g_cnt[NN];              // zero-init at load; re-zeroed by scatter
__device__ int  g_off[NN + 1];
__device__ int  g_cur[NN];
__device__ int  g_bsum[NBLK];
__device__ int2 g_ev[EE];               // (src, float_as_int(v)) sorted by dst

__device__ __align__(16) float g_YY[NN * 32];   // interleaved [Y0[16] | Yd[16]]
__device__ __align__(16) float g_R1[NN * HH];   // x @ root1 + b1
__device__ __align__(16) float g_ZZ[NN * 24];   // interleaved [Z0[12] | Zd[12]]
__device__ __align__(16) float g_R2[NN * CP];   // h @ root2 + b2 (padded)

// ---------------- dtype detect (1 block) --------------------------------------
__global__ void k_detect(const int* __restrict__ ei32) {
    __shared__ int s_any;
    if (threadIdx.x == 0) s_any = 0;
    __syncthreads();
    int v = 0;
    for (int j = 2 * threadIdx.x + 1; j < 4096; j += 2 * blockDim.x) v |= ei32[j];
    if (v) atomicOr(&s_any, 1);
    __syncthreads();
    if (threadIdx.x == 0) g_is64 = (s_any == 0) ? 1 : 0;
}

// ---------------- histogram (g_cnt pre-zeroed) --------------------------------
__global__ void k_hist(const void* __restrict__ ei) {
    int e = blockIdx.x * blockDim.x + threadIdx.x;
    if (e >= EE) return;
    int d = g_is64 ? (int)((const long long*)ei)[EE + e] : ((const int*)ei)[EE + e];
    atomicAdd(&g_cnt[d], 1);
}

// Phase 1: per-block (1024-wide) exclusive scan of g_cnt -> g_off, block sums.
__global__ void k_scan_blk() {
    __shared__ int wsum[32];
    int i = blockIdx.x * 1024 + threadIdx.x;
    int lane = threadIdx.x & 31, wid = threadIdx.x >> 5;
    int v = (i < NN) ? g_cnt[i] : 0;
    int s = v;
#pragma unroll
    for (int d = 1; d < 32; d <<= 1) {
        int t = __shfl_up_sync(0xffffffffu, s, d);
        if (lane >= d) s += t;
    }
    if (lane == 31) wsum[wid] = s;
    __syncthreads();
    if (wid == 0) {
        int ws = wsum[lane];
#pragma unroll
        for (int d = 1; d < 32; d <<= 1) {
            int t = __shfl_up_sync(0xffffffffu, ws, d);
            if (lane >= d) ws += t;
        }
        wsum[lane] = ws;    // inclusive across warps
    }
    __syncthreads();
    int wpre = (wid == 0) ? 0 : wsum[wid - 1];
    if (i < NN) g_off[i] = wpre + s - v;          // block-local exclusive
    if (threadIdx.x == 1023) g_bsum[blockIdx.x] = wsum[31];
}

// Phase 2+3 fused: every block re-derives block prefixes from g_bsum in shared.
__global__ void k_scan_add() {
    __shared__ int sb[NBLK];
    for (int t = threadIdx.x; t < NBLK; t += blockDim.x) sb[t] = g_bsum[t];
    __syncthreads();
    int i = blockIdx.x * blockDim.x + threadIdx.x;
    if (i < NN) {
        int nb = i >> 10;
        int pre = 0;
        for (int j = 0; j < nb; j++) pre += sb[j];
        int o = g_off[i] + pre;
        g_off[i] = o;
        g_cur[i] = o;
    }
    if (i == 0) {
        int tot = 0;
        for (int j = 0; j < NBLK; j++) tot += sb[j];
        g_off[NN] = tot;
    }
}

// ---------------- fused: edge scatter (+ re-zero g_cnt) | layer-1 node GEMM ----
__global__ void k_scatter_node1(const void* __restrict__ ei, const float* __restrict__ attr,
                                const float* __restrict__ x, const float* __restrict__ W1,
                                const float* __restrict__ root1, const float* __restrict__ b1) {
    if (blockIdx.x < SBLK) {
        // -------- scatter part --------
        int e = blockIdx.x * 256 + threadIdx.x;
        if (e < NN) g_cnt[e] = 0;       // reset histogram for next replay
        int s, d;
        if (g_is64) {
            const long long* p = (const long long*)ei;
            s = (int)p[e];
            d = (int)p[EE + e];
        } else {
            const int* p = (const int*)ei;
            s = p[e];
            d = p[EE + e];
        }
        float v = attr[e];              // K=2 -> v = attr * (K-1) = attr
        int pos = atomicAdd(&g_cur[d], 1);
        g_ev[pos] = make_int2(s, __float_as_int(v));
        return;
    }
    // -------- node1 part --------
    __shared__ float sW0[FI * HH], sWd[FI * HH], sR[FI * HH], sB[HH];
    for (int i = threadIdx.x; i < FI * HH; i += blockDim.x) {
        float w0 = W1[i];
        sW0[i] = w0;
        sWd[i] = W1[FI * HH + i] - w0;
        sR[i]  = root1[i];
    }
    if (threadIdx.x < HH) sB[threadIdx.x] = b1[threadIdx.x];
    __syncthreads();

    int n = (blockIdx.x - SBLK) * 256 + threadIdx.x;
    if (n >= NN) return;

    float xr[FI];
    const float4* xp = (const float4*)(x + (size_t)n * FI);
#pragma unroll
    for (int i = 0; i < FI / 4; i++) {
        float4 t = xp[i];
        xr[4 * i + 0] = t.x; xr[4 * i + 1] = t.y;
        xr[4 * i + 2] = t.z; xr[4 * i + 3] = t.w;
    }

    float4 y0[4], yd[4], r1[4];
#pragma unroll
    for (int j = 0; j < 4; j++) {
        y0[j] = make_float4(0.f, 0.f, 0.f, 0.f);
        yd[j] = make_float4(0.f, 0.f, 0.f, 0.f);
        r1[j] = ((const float4*)sB)[j];
    }
#pragma unroll
    for (int i = 0; i < FI; i++) {
        float xi = xr[i];
        const float4* w0 = (const float4*)(sW0 + i * HH);
        const float4* wd = (const float4*)(sWd + i * HH);
        const float4* wr = (const float4*)(sR + i * HH);
#pragma unroll
        for (int j = 0; j < 4; j++) {
            float4 a = w0[j], b = wd[j], c = wr[j];
            y0[j].x = fmaf(xi, a.x, y0[j].x); y0[j].y = fmaf(xi, a.y, y0[j].y);
            y0[j].z = fmaf(xi, a.z, y0[j].z); y0[j].w = fmaf(xi, a.w, y0[j].w);
            yd[j].x = fmaf(xi, b.x, yd[j].x); yd[j].y = fmaf(xi, b.y, yd[j].y);
            yd[j].z = fmaf(xi, b.z, yd[j].z); yd[j].w = fmaf(xi, b.w, yd[j].w);
            r1[j].x = fmaf(xi, c.x, r1[j].x); r1[j].y = fmaf(xi, c.y, r1[j].y);
            r1[j].z = fmaf(xi, c.z, r1[j].z); r1[j].w = fmaf(xi, c.w, r1[j].w);
        }
    }
    float4* oy = (float4*)(g_YY + (size_t)n * 32);
    float4* orr = (float4*)(g_R1 + (size_t)n * HH);
#pragma unroll
    for (int j = 0; j < 4; j++) { oy[j] = y0[j]; oy[4 + j] = yd[j]; orr[j] = r1[j]; }
}

// ---------------- layer-1 gather + ELU + layer-2 node precompute (fused) -------
// Warp per node. Gather phase: lane<16 accumulates Y0, lane>=16 v*Yd (one 128B
// coalesced load per edge, unroll 8). Then compute h in lanes 0-15 and directly
// produce the layer-2 records ZZ=[Z0|Zd] and R2 via shfl-broadcast matvec.
__global__ void k_gath1z(const float* __restrict__ W2, const float* __restrict__ root2,
                         const float* __restrict__ b2) {
    __shared__ float sZ0[HH * CP + 1], sZd[HH * CP + 1], sRw[HH * CP + 1], sB2[CP];
    for (int idx = threadIdx.x; idx < HH * CP; idx += blockDim.x) {
        int i = idx / CP, c = idx % CP;
        float w0 = (c < CC) ? W2[i * CC + c] : 0.f;
        float w1 = (c < CC) ? W2[HH * CC + i * CC + c] : 0.f;
        sZ0[idx] = w0;
        sZd[idx] = w1 - w0;
        sRw[idx] = (c < CC) ? root2[i * CC + c] : 0.f;
    }
    if (threadIdx.x < CP) sB2[threadIdx.x] = (threadIdx.x < CC) ? b2[threadIdx.x] : 0.f;
    __syncthreads();

    int w = (blockIdx.x * blockDim.x + threadIdx.x) >> 5;
    int lane = threadIdx.x & 31;
    if (w >= NN) return;
    int beg = g_off[w], end = g_off[w + 1];

    float acc = 0.f;
    int i = beg;
    for (; i + 7 < end; i += 8) {
        int2 e0 = g_ev[i],     e1 = g_ev[i + 1], e2 = g_ev[i + 2], e3 = g_ev[i + 3];
        int2 e4 = g_ev[i + 4], e5 = g_ev[i + 5], e6 = g_ev[i + 6], e7 = g_ev[i + 7];
        float v0 = g_YY[(size_t)e0.x * 32 + lane];
        float v1 = g_YY[(size_t)e1.x * 32 + lane];
        float v2 = g_YY[(size_t)e2.x * 32 + lane];
        float v3 = g_YY[(size_t)e3.x * 32 + lane];
        float v4 = g_YY[(size_t)e4.x * 32 + lane];
        float v5 = g_YY[(size_t)e5.x * 32 + lane];
        float v6 = g_YY[(size_t)e6.x * 32 + lane];
        float v7 = g_YY[(size_t)e7.x * 32 + lane];
        bool lo = (lane < 16);
        acc = fmaf(lo ? 1.f : __int_as_float(e0.y), v0, acc);
        acc = fmaf(lo ? 1.f : __int_as_float(e1.y), v1, acc);
        acc = fmaf(lo ? 1.f : __int_as_float(e2.y), v2, acc);
        acc = fmaf(lo ? 1.f : __int_as_float(e3.y), v3, acc);
        acc = fmaf(lo ? 1.f : __int_as_float(e4.y), v4, acc);
        acc = fmaf(lo ? 1.f : __int_as_float(e5.y), v5, acc);
        acc = fmaf(lo ? 1.f : __int_as_float(e6.y), v6, acc);
        acc = fmaf(lo ? 1.f : __int_as_float(e7.y), v7, acc);
    }
    for (; i < end; i++) {
        int2 e0 = g_ev[i];
        float v0 = g_YY[(size_t)e0.x * 32 + lane];
        acc = fmaf((lane < 16) ? 1.f : __int_as_float(e0.y), v0, acc);
    }
    acc += __shfl_xor_sync(0xffffffffu, acc, 16);

    // h on lanes 0-15
    float h = 0.f;
    if (lane < 16) {
        float rdeg = 1.f / fmaxf((float)(end - beg), 1.f);
        float t = fmaf(acc, rdeg, g_R1[(size_t)w * HH + lane]);
        h = (t > 0.f) ? t : expm1f(t);
    }

    // layer-2 node precompute via shfl broadcast:
    //   lanes 0-11:  a0 = Z0 col, a1 = root2 col;  lanes 12-23: a0 = Zd col.
    int c = (lane < 12) ? lane : ((lane < 24) ? lane - 12 : 0);
    float a0 = 0.f, a1 = 0.f;
#pragma unroll
    for (int ii = 0; ii < HH; ii++) {
        float hi = __shfl_sync(0xffffffffu, h, ii);
        if (lane < 12) {
            a0 = fmaf(hi, sZ0[ii * CP + c], a0);
            a1 = fmaf(hi, sRw[ii * CP + c], a1);
        } else {
            a0 = fmaf(hi, sZd[ii * CP + c], a0);
        }
    }
    if (lane < 24) g_ZZ[(size_t)w * 24 + lane] = a0;
    if (lane < 12) g_R2[(size_t)w * CP + lane] = a1 + sB2[lane];
}

// ---------------- layer-2 gather + log_softmax: warp per node ------------------
__global__ void k_gath2(float* __restrict__ out) {
    int w = (blockIdx.x * blockDim.x + threadIdx.x) >> 5;
    int lane = threadIdx.x & 31;
    if (w >= NN) return;
    int beg = g_off[w], end = g_off[w + 1];
    bool act = (lane < 24);
    bool lo = (lane < 12);

    float acc = 0.f;
    int i = beg;
    for (; i + 7 < end; i += 8) {
        int2 e0 = g_ev[i],     e1 = g_ev[i + 1], e2 = g_ev[i + 2], e3 = g_ev[i + 3];
        int2 e4 = g_ev[i + 4], e5 = g_ev[i + 5], e6 = g_ev[i + 6], e7 = g_ev[i + 7];
        float v0 = act ? g_ZZ[(size_t)e0.x * 24 + lane] : 0.f;
        float v1 = act ? g_ZZ[(size_t)e1.x * 24 + lane] : 0.f;
        float v2 = act ? g_ZZ[(size_t)e2.x * 24 + lane] : 0.f;
        float v3 = act ? g_ZZ[(size_t)e3.x * 24 + lane] : 0.f;
        float v4 = act ? g_ZZ[(size_t)e4.x * 24 + lane] : 0.f;
        float v5 = act ? g_ZZ[(size_t)e5.x * 24 + lane] : 0.f;
        float v6 = act ? g_ZZ[(size_t)e6.x * 24 + lane] : 0.f;
        float v7 = act ? g_ZZ[(size_t)e7.x * 24 + lane] : 0.f;
        acc = fmaf(lo ? 1.f : __int_as_float(e0.y), v0, acc);
        acc = fmaf(lo ? 1.f : __int_as_float(e1.y), v1, acc);
        acc = fmaf(lo ? 1.f : __int_as_float(e2.y), v2, acc);
        acc = fmaf(lo ? 1.f : __int_as_float(e3.y), v3, acc);
        acc = fmaf(lo ? 1.f : __int_as_float(e4.y), v4, acc);
        acc = fmaf(lo ? 1.f : __int_as_float(e5.y), v5, acc);
        acc = fmaf(lo ? 1.f : __int_as_float(e6.y), v6, acc);
        acc = fmaf(lo ? 1.f : __int_as_float(e7.y), v7, acc);
    }
    for (; i < end; i++) {
        int2 e0 = g_ev[i];
        float v0 = act ? g_ZZ[(size_t)e0.x * 24 + lane] : 0.f;
        acc = fmaf(lo ? 1.f : __int_as_float(e0.y), v0, acc);
    }
    float other = __shfl_down_sync(0xffffffffu, acc, 12);
    float rdeg = 1.f / fmaxf((float)(end - beg), 1.f);
    float u = 0.f;
    if (lane < CP)
        u = fmaf(acc + other, rdeg, g_R2[(size_t)w * CP + lane]);

    float um = (lane < CC) ? u : -1e30f;
#pragma unroll
    for (int d = 1; d < 16; d <<= 1)
        um = fmaxf(um, __shfl_xor_sync(0xffffffffu, um, d, 16));
    float ex = (lane < CC) ? __expf(u - um) : 0.f;
    float s = ex;
#pragma unroll
    for (int d = 1; d < 16; d <<= 1)
        s += __shfl_xor_sync(0xffffffffu, s, d, 16);
    float lse = um + logf(s);
    if (lane < CC) out[(size_t)w * CC + lane] = u - lse;
}

// ---------------- launch ------------------------------------------------------
extern "C" void kernel_launch(void* const* d_in, const int* in_sizes, int n_in,
                              void* d_out, int out_size) {
    const float* x     = (const float*)d_in[0];
    const void*  ei    = d_in[1];
    const float* attr  = (const float*)d_in[2];
    const float* W1    = (const float*)d_in[3];
    const float* root1 = (const float*)d_in[4];
    const float* b1    = (const float*)d_in[5];
    const float* W2    = (const float*)d_in[6];
    const float* root2 = (const float*)d_in[7];
    const float* b2    = (const float*)d_in[8];
    float* out = (float*)d_out;

    k_detect<<<1, 256>>>((const int*)ei);
    k_hist<<<(EE + 255) / 256, 256>>>(ei);
    k_scan_blk<<<NBLK, 1024>>>();
    k_scan_add<<<N1BLK, 256>>>();
    k_scatter_node1<<<SBLK + N1BLK, 256>>>(ei, attr, x, W1, root1, b1);
    k_gath1z<<<(NN + 7) / 8, 256>>>(W2, root2, b2);
    k_gath2<<<(NN + 7) / 8, 256>>>(out);
}